// round 1
// baseline (speedup 1.0000x reference)
#include <cuda_runtime.h>

#define BATCH 16
#define DIM 64
#define HH 256
#define WW 256
#define KATT 4
#define KS 5
#define HO 127
#define WO 127

// ---- device scratch (no allocations allowed) ----
__device__ float g_pooled[BATCH * DIM];
__device__ float g_att[BATCH * KATT];
__device__ float g_aggb[BATCH * DIM];
__device__ float g_aggw[BATCH * DIM * DIM * KS * KS];  // layout (b, o, i, kh*5+kw)

// ============================================================
// 1) Global average pool: pooled[b][c] = mean(x[b,c,:,:])
// ============================================================
__global__ void pool_kernel(const float* __restrict__ x) {
    int bc = blockIdx.x;  // 0 .. B*DIM-1
    const float4* p4 = (const float4*)(x + (size_t)bc * HH * WW);
    const int n4 = HH * WW / 4;  // 16384
    float s = 0.f;
    for (int i = threadIdx.x; i < n4; i += 256) {
        float4 v = p4[i];
        s += (v.x + v.y) + (v.z + v.w);
    }
    __shared__ float red[256];
    red[threadIdx.x] = s;
    __syncthreads();
    for (int k = 128; k > 0; k >>= 1) {
        if (threadIdx.x < k) red[threadIdx.x] += red[threadIdx.x + k];
        __syncthreads();
    }
    if (threadIdx.x == 0) g_pooled[bc] = red[0] * (1.0f / (HH * WW));
}

// ============================================================
// 2) Attention: fc1 -> relu -> fc2 -> softmax; agg_b = att @ bias
// ============================================================
__global__ void att_kernel(const float* __restrict__ fc1_w,
                           const float* __restrict__ fc1_b,
                           const float* __restrict__ fc2_w,
                           const float* __restrict__ fc2_b,
                           const float* __restrict__ bias) {
    int t = threadIdx.x;
    __shared__ float s_att[BATCH * KATT];
    if (t < BATCH) {
        int b = t;
        float a[KATT];
        #pragma unroll
        for (int k = 0; k < KATT; k++) {
            float s = fc1_b[k];
            for (int c = 0; c < DIM; c++)
                s = fmaf(g_pooled[b * DIM + c], fc1_w[k * DIM + c], s);
            a[k] = fmaxf(s, 0.f);
        }
        float z[KATT];
        float m = -1e30f;
        #pragma unroll
        for (int j = 0; j < KATT; j++) {
            float s = fc2_b[j];
            #pragma unroll
            for (int k = 0; k < KATT; k++)
                s = fmaf(a[k], fc2_w[j * KATT + k], s);
            z[j] = s;
            m = fmaxf(m, s);
        }
        float den = 0.f;
        #pragma unroll
        for (int j = 0; j < KATT; j++) { z[j] = expf(z[j] - m); den += z[j]; }
        float inv = 1.0f / den;
        #pragma unroll
        for (int j = 0; j < KATT; j++) {
            float v = z[j] * inv;
            s_att[b * KATT + j] = v;
            g_att[b * KATT + j] = v;
        }
    }
    __syncthreads();
    for (int idx = t; idx < BATCH * DIM; idx += 256) {
        int b = idx / DIM, o = idx % DIM;
        float s = 0.f;
        #pragma unroll
        for (int k = 0; k < KATT; k++)
            s = fmaf(s_att[b * KATT + k], bias[k * DIM + o], s);
        g_aggb[idx] = s;
    }
}

// ============================================================
// 3) Mix kernel bank: agg_w[b,o,i,p] = sum_k att[b,k] * weight[k,o,i,p]
//    Also write w_ret output: w_ret[(b*64+o), p, i]
// ============================================================
__global__ void aggw_kernel(const float* __restrict__ weight,
                            float* __restrict__ w_ret) {
    int idx = blockIdx.x * 256 + threadIdx.x;  // exactly B*DIM*DIM*25
    int p = idx % 25;
    int r = idx / 25;
    int i = r % DIM; r /= DIM;
    int o = r % DIM;
    int b = r / DIM;
    float s = 0.f;
    #pragma unroll
    for (int k = 0; k < KATT; k++)
        s = fmaf(g_att[b * KATT + k],
                 weight[(((size_t)(k * DIM + o) * DIM + i) * 25) + p], s);
    g_aggw[idx] = s;
    w_ret[((size_t)(b * DIM + o) * 25 + p) * DIM + i] = s;
}

// ============================================================
// 4) Per-sample conv: 64ch -> 64ch, 5x5, stride 2, pad 1.
//    Block: one (b, group of 16 out-channels), 32x16 output pixels.
//    Threads (16,16): each thread -> 2 adjacent output cols x 16 channels.
// ============================================================
__global__ void __launch_bounds__(256, 2)
conv_kernel(const float* __restrict__ x, float* __restrict__ out) {
    const int tz = blockIdx.z;
    const int b = tz >> 2;
    const int og = tz & 3;
    const int ox0 = blockIdx.x * 32;
    const int oy0 = blockIdx.y * 16;
    const int tx = threadIdx.x;
    const int ty = threadIdx.y;
    const int tid = ty * 16 + tx;

    __shared__ float s_in[35 * 68];
    __shared__ float s_w[16 * 25];

    float acc0[16], acc1[16];
    #pragma unroll
    for (int o = 0; o < 16; o++) { acc0[o] = 0.f; acc1[o] = 0.f; }

    const int ix0 = ox0 * 2 - 1;
    const int iy0 = oy0 * 2 - 1;
    const float* xb = x + (size_t)b * DIM * HH * WW;
    const float* wb = g_aggw + (size_t)(b * DIM + og * 16) * DIM * 25;

    for (int ci = 0; ci < DIM; ci++) {
        // stage input tile 35x67 (zero-padded at borders)
        const float* xc = xb + (size_t)ci * HH * WW;
        for (int idx = tid; idx < 35 * 67; idx += 256) {
            int r = idx / 67;
            int c = idx - r * 67;
            int iy = iy0 + r, ix = ix0 + c;
            float v = 0.f;
            if (iy >= 0 && iy < HH && ix >= 0 && ix < WW)
                v = xc[iy * WW + ix];
            s_in[r * 68 + c] = v;
        }
        // stage 16 x 25 weights for this input channel
        for (int idx = tid; idx < 400; idx += 256) {
            int o = idx / 25, k = idx - o * 25;
            s_w[idx] = wb[(o * DIM + ci) * 25 + k];
        }
        __syncthreads();

        // input window for this thread's 2 output pixels (cols ox0+2tx, +1)
        float xin[5][7];
        #pragma unroll
        for (int r = 0; r < 5; r++)
            #pragma unroll
            for (int c = 0; c < 7; c++)
                xin[r][c] = s_in[(2 * ty + r) * 68 + 4 * tx + c];

        #pragma unroll
        for (int o = 0; o < 16; o++) {
            float a0 = acc0[o], a1 = acc1[o];
            #pragma unroll
            for (int kh = 0; kh < 5; kh++)
                #pragma unroll
                for (int kw = 0; kw < 5; kw++) {
                    float w = s_w[o * 25 + kh * 5 + kw];
                    a0 = fmaf(xin[kh][kw], w, a0);
                    a1 = fmaf(xin[kh][kw + 2], w, a1);
                }
            acc0[o] = a0; acc1[o] = a1;
        }
        __syncthreads();
    }

    const int oy = oy0 + ty;
    const int ox_a = ox0 + 2 * tx;
    const int ox_b = ox_a + 1;
    if (oy < HO) {
        #pragma unroll
        for (int o = 0; o < 16; o++) {
            int oglob = og * 16 + o;
            float bb = g_aggb[b * DIM + oglob];
            size_t base = ((size_t)(b * DIM + oglob)) * HO * WO + (size_t)oy * WO;
            if (ox_a < WO) out[base + ox_a] = acc0[o] + bb;
            if (ox_b < WO) out[base + ox_b] = acc1[o] + bb;
        }
    }
}

// ============================================================
extern "C" void kernel_launch(void* const* d_in, const int* in_sizes, int n_in,
                              void* d_out, int out_size) {
    const float* x     = (const float*)d_in[0];
    const float* fc1_w = (const float*)d_in[1];
    const float* fc1_b = (const float*)d_in[2];
    const float* fc2_w = (const float*)d_in[3];
    const float* fc2_b = (const float*)d_in[4];
    const float* weight= (const float*)d_in[5];
    const float* bias  = (const float*)d_in[6];
    float* out = (float*)d_out;
    float* w_ret = out + (size_t)BATCH * DIM * HO * WO;  // 16,516,096

    pool_kernel<<<BATCH * DIM, 256>>>(x);
    att_kernel<<<1, 256>>>(fc1_w, fc1_b, fc2_w, fc2_b, bias);
    aggw_kernel<<<(BATCH * DIM * DIM * 25) / 256, 256>>>(weight, w_ret);
    dim3 cgrid(4, 8, BATCH * 4);
    dim3 cblk(16, 16);
    conv_kernel<<<cgrid, cblk>>>(x, out);
}

// round 4
// speedup vs baseline: 1.5980x; 1.5980x over previous
#include <cuda_runtime.h>
#include <cstdint>

#define BATCH 16
#define DIM 64
#define HH 256
#define WW 256
#define KATT 4
#define KS 5
#define HO 127
#define WO 127

#define SROW 132          // padded smem row stride (floats), 16B-aligned
#define IN_ROWS 11
#define IN_COLS 131

// ---- device scratch (no allocations allowed) ----
__device__ float g_pooled[BATCH * DIM];
__device__ float g_att[BATCH * KATT];
__device__ float g_aggb[BATCH * DIM];
// mixed weights, conv-friendly layout: [b][ci][p][o], o contiguous
__device__ float g_aggw2[BATCH * DIM * 25 * DIM];

// ---------------- PTX helpers ----------------
__device__ __forceinline__ void cp_async4(uint32_t dst, const void* src, bool ok) {
    asm volatile("cp.async.ca.shared.global [%0], [%1], 4, %2;"
                 :: "r"(dst), "l"(src), "r"(ok ? 4 : 0));
}
__device__ __forceinline__ void cp_async16(uint32_t dst, const void* src) {
    asm volatile("cp.async.cg.shared.global [%0], [%1], 16;"
                 :: "r"(dst), "l"(src));
}
__device__ __forceinline__ void cp_commit() {
    asm volatile("cp.async.commit_group;");
}
template <int N>
__device__ __forceinline__ void cp_wait() {
    asm volatile("cp.async.wait_group %0;" :: "n"(N));
}
__device__ __forceinline__ unsigned long long pack_dup(float v) {
    unsigned long long r;
    uint32_t b = __float_as_uint(v);
    asm("mov.b64 %0, {%1, %1};" : "=l"(r) : "r"(b));
    return r;
}
__device__ __forceinline__ void fma2(unsigned long long& acc,
                                     unsigned long long a,
                                     unsigned long long b) {
    asm("fma.rn.f32x2 %0, %1, %2, %0;" : "+l"(acc) : "l"(a), "l"(b));
}
__device__ __forceinline__ void unpack2(unsigned long long v, float& lo, float& hi) {
    uint32_t l, h;
    asm("mov.b64 {%0, %1}, %2;" : "=r"(l), "=r"(h) : "l"(v));
    lo = __uint_as_float(l);
    hi = __uint_as_float(h);
}

// ============================================================
// 1) Global average pool
// ============================================================
__global__ void pool_kernel(const float* __restrict__ x) {
    int bc = blockIdx.x;  // 0 .. B*DIM-1
    const float4* p4 = (const float4*)(x + (size_t)bc * HH * WW);
    const int n4 = HH * WW / 4;
    float s = 0.f;
    for (int i = threadIdx.x; i < n4; i += 256) {
        float4 v = p4[i];
        s += (v.x + v.y) + (v.z + v.w);
    }
    __shared__ float red[256];
    red[threadIdx.x] = s;
    __syncthreads();
    for (int k = 128; k > 0; k >>= 1) {
        if (threadIdx.x < k) red[threadIdx.x] += red[threadIdx.x + k];
        __syncthreads();
    }
    if (threadIdx.x == 0) g_pooled[bc] = red[0] * (1.0f / (HH * WW));
}

// ============================================================
// 2) Attention + agg bias
// ============================================================
__global__ void att_kernel(const float* __restrict__ fc1_w,
                           const float* __restrict__ fc1_b,
                           const float* __restrict__ fc2_w,
                           const float* __restrict__ fc2_b,
                           const float* __restrict__ bias) {
    int t = threadIdx.x;
    __shared__ float s_att[BATCH * KATT];
    if (t < BATCH) {
        int b = t;
        float a[KATT];
        #pragma unroll
        for (int k = 0; k < KATT; k++) {
            float s = fc1_b[k];
            for (int c = 0; c < DIM; c++)
                s = fmaf(g_pooled[b * DIM + c], fc1_w[k * DIM + c], s);
            a[k] = fmaxf(s, 0.f);
        }
        float z[KATT];
        float m = -1e30f;
        #pragma unroll
        for (int j = 0; j < KATT; j++) {
            float s = fc2_b[j];
            #pragma unroll
            for (int k = 0; k < KATT; k++)
                s = fmaf(a[k], fc2_w[j * KATT + k], s);
            z[j] = s;
            m = fmaxf(m, s);
        }
        float den = 0.f;
        #pragma unroll
        for (int j = 0; j < KATT; j++) { z[j] = expf(z[j] - m); den += z[j]; }
        float inv = 1.0f / den;
        #pragma unroll
        for (int j = 0; j < KATT; j++) {
            float v = z[j] * inv;
            s_att[b * KATT + j] = v;
            g_att[b * KATT + j] = v;
        }
    }
    __syncthreads();
    for (int idx = t; idx < BATCH * DIM; idx += 256) {
        int b = idx / DIM, o = idx % DIM;
        float s = 0.f;
        #pragma unroll
        for (int k = 0; k < KATT; k++)
            s = fmaf(s_att[b * KATT + k], bias[k * DIM + o], s);
        g_aggb[idx] = s;
    }
}

// ============================================================
// 3) Mix kernel bank -> g_aggw2[b][i][p][o] (+ w_ret output)
//    idx = (((b*64 + i)*25 + p)*64 + o)
// ============================================================
__global__ void aggw_kernel(const float* __restrict__ weight,
                            float* __restrict__ w_ret) {
    int idx = blockIdx.x * 256 + threadIdx.x;
    int o = idx & 63;
    int r = idx >> 6;
    int p = r % 25; r /= 25;
    int i = r & 63;
    int b = r >> 6;
    float s = 0.f;
    #pragma unroll
    for (int k = 0; k < KATT; k++)
        s = fmaf(g_att[b * KATT + k],
                 weight[(((size_t)(k * DIM + o) * DIM + i) * 25) + p], s);
    g_aggw2[idx] = s;
    w_ret[((size_t)(b * DIM + o) * 25 + p) * DIM + i] = s;
}

// ============================================================
// 4) Conv: block = (b, 64x4 output tile, all 64 oc).
//    256 threads: colg = tid&7 (8 out cols each), row = (tid>>3)&3,
//    ocg = tid>>5 (8 out channels each, as 4 f32x2 pairs).
//    cp.async double-buffered smem; inner loop is pure FFMA2.
// ============================================================
__global__ void __launch_bounds__(256, 2)
conv_kernel(const float* __restrict__ x, float* __restrict__ out) {
    __shared__ __align__(16) float s_in[2][IN_ROWS * SROW];
    __shared__ __align__(16) float s_w[2][25 * 64];

    const int tid = threadIdx.x;
    const int colg = tid & 7;
    const int row = (tid >> 3) & 3;
    const int ocg = tid >> 5;

    const int bx = blockIdx.x;          // 0..1   (64 out cols each)
    const int by = blockIdx.y;          // 0..31  (4 out rows each)
    const int b  = blockIdx.z;          // batch

    const int ix0 = 128 * bx - 1;
    const int iy0 = 8 * by - 1;
    const float* xb = x + (size_t)b * DIM * HH * WW;
    const float* wb = g_aggw2 + (size_t)b * DIM * 1600;

    uint32_t in_s[2], w_s[2];
    in_s[0] = (uint32_t)__cvta_generic_to_shared(&s_in[0][0]);
    in_s[1] = (uint32_t)__cvta_generic_to_shared(&s_in[1][0]);
    w_s[0]  = (uint32_t)__cvta_generic_to_shared(&s_w[0][0]);
    w_s[1]  = (uint32_t)__cvta_generic_to_shared(&s_w[1][0]);

    // stage loader for input channel ci into buffer bf
    auto load_stage = [&](int ci, int bf) {
        const float* xc = xb + (size_t)ci * HH * WW;
        #pragma unroll
        for (int it = 0; it < 6; it++) {
            int idx = tid + it * 256;
            if (idx < IN_ROWS * IN_COLS) {
                int r = idx / IN_COLS;
                int c = idx - r * IN_COLS;
                int iy = iy0 + r, ix = ix0 + c;
                bool ok = ((unsigned)iy < HH) && ((unsigned)ix < WW);
                const float* src = ok ? (xc + iy * WW + ix) : xc;
                cp_async4(in_s[bf] + (uint32_t)(r * SROW + c) * 4u, src, ok);
            }
        }
        const float* wsrc = wb + ci * 1600;
        #pragma unroll
        for (int it = 0; it < 2; it++) {
            int idx = tid + it * 256;
            if (idx < 400)
                cp_async16(w_s[bf] + (uint32_t)idx * 16u, wsrc + idx * 4);
        }
    };

    unsigned long long acc[8][4];
    #pragma unroll
    for (int k = 0; k < 8; k++)
        #pragma unroll
        for (int u = 0; u < 4; u++) acc[k][u] = 0ull;

    load_stage(0, 0);
    cp_commit();

    for (int ci = 0; ci < DIM; ci++) {
        const int cur = ci & 1;
        if (ci + 1 < DIM) {
            load_stage(ci + 1, cur ^ 1);
            cp_commit();
            cp_wait<1>();
        } else {
            cp_wait<0>();
        }
        __syncthreads();

        const float* si = &s_in[cur][0];
        const float* sw = &s_w[cur][0];

        #pragma unroll
        for (int kh = 0; kh < 5; kh++) {
            // 20 consecutive input floats for this thread's 8 output cols
            const float4* xr = (const float4*)(si + (2 * row + kh) * SROW + 16 * colg);
            float xv[20];
            #pragma unroll
            for (int q = 0; q < 5; q++) {
                float4 v = xr[q];
                xv[4 * q + 0] = v.x; xv[4 * q + 1] = v.y;
                xv[4 * q + 2] = v.z; xv[4 * q + 3] = v.w;
            }
            #pragma unroll
            for (int kw = 0; kw < 5; kw++) {
                const unsigned long long* wp =
                    (const unsigned long long*)(sw + (kh * 5 + kw) * 64 + ocg * 8);
                unsigned long long w2[4];
                #pragma unroll
                for (int u = 0; u < 4; u++) w2[u] = wp[u];
                #pragma unroll
                for (int k = 0; k < 8; k++) {
                    unsigned long long x2 = pack_dup(xv[2 * k + kw]);
                    #pragma unroll
                    for (int u = 0; u < 4; u++) fma2(acc[k][u], x2, w2[u]);
                }
            }
        }
        __syncthreads();
    }

    // ---- epilogue (scalar stores: out row base is only 4B-aligned in general) ----
    const int oy = 4 * by + row;
    if (oy < HO) {
        const int oxb = 64 * bx + 8 * colg;
        #pragma unroll
        for (int u = 0; u < 4; u++) {
            const int oc0 = ocg * 8 + 2 * u;
            const float b0 = g_aggb[b * DIM + oc0];
            const float b1 = g_aggb[b * DIM + oc0 + 1];
            size_t base0 = ((size_t)(b * DIM + oc0)) * HO * WO + (size_t)oy * WO + oxb;
            size_t base1 = base0 + (size_t)HO * WO;
            #pragma unroll
            for (int k = 0; k < 8; k++) {
                float lo, hi;
                unpack2(acc[k][u], lo, hi);
                if (oxb + k < WO) {
                    out[base0 + k] = lo + b0;
                    out[base1 + k] = hi + b1;
                }
            }
        }
    }
}

// ============================================================
extern "C" void kernel_launch(void* const* d_in, const int* in_sizes, int n_in,
                              void* d_out, int out_size) {
    const float* x     = (const float*)d_in[0];
    const float* fc1_w = (const float*)d_in[1];
    const float* fc1_b = (const float*)d_in[2];
    const float* fc2_w = (const float*)d_in[3];
    const float* fc2_b = (const float*)d_in[4];
    const float* weight= (const float*)d_in[5];
    const float* bias  = (const float*)d_in[6];
    float* out = (float*)d_out;
    float* w_ret = out + (size_t)BATCH * DIM * HO * WO;

    pool_kernel<<<BATCH * DIM, 256>>>(x);
    att_kernel<<<1, 256>>>(fc1_w, fc1_b, fc2_w, fc2_b, bias);
    aggw_kernel<<<(BATCH * DIM * DIM * 25) / 256, 256>>>(weight, w_ret);
    dim3 cgrid(2, 32, BATCH);
    conv_kernel<<<cgrid, 256>>>(x, out);
}